// round 13
// baseline (speedup 1.0000x reference)
#include <cuda_runtime.h>
#include <cuda_bf16.h>

// LSTMStateBufferCell:
//   pos[b]  = sum_s hidden_masks[s,b]            (pos in [0,S])
//   prev    = mod(pos-1, S+1)
//   stack_X = [init_X ; X]  (index 0 = init row)
//   out_h[b,:] = stack_h[prev]*a + stack_h[pos]*(1-a),  a = |op[b]|
//   out_c[b,:] = stack_c[prev]*a + stack_c[pos]*(1-a)
// Output: f32 [2, B, H] (hidden then cell).
//
// Final configuration, synthesizing 12 rounds of evidence:
//   Fast path (S==1024, H==1024): one block per batch element, 1024 threads.
//   - pos: exactly ONE mask LDG per thread (each of the 1024 mask lines is
//     touched exactly once per block -> minimal L1tex wavefront count; the
//     R11 experiment proved per-warp redundant strided reads cost ~6us)
//     -> one REDUX.SUM -> ONE __syncthreads -> serial sum of 32 warp partials.
//   - copy: 512 threads per output (hidden/cell), exactly one float2 load +
//     one float2 store each. a in {0,1} => pure row select (halves gather
//     traffic); general blend fallback preserved for any a.
//   This variant had the best profiled kernel time of all rounds (5.95us,
//   occ 44.9%, issue 18.8%). dur_us itself is pinned at the ~6.6-6.9us
//   graph-replay floor and no longer distinguishes sane variants.

#define NTH 1024

__global__ __launch_bounds__(NTH)
void lstm_state_kernel_fast(
    const float* __restrict__ hiddens,
    const float* __restrict__ cells,
    const float* __restrict__ init_hidden,
    const float* __restrict__ init_cell,
    const int*   __restrict__ masks,
    const int*   __restrict__ op,
    float* __restrict__ out,
    int S, int B, int H)     // S==1024, H==1024
{
    const int b   = blockIdx.x;
    const int tid = threadIdx.x;

    // Independent of the mask chain — issue first.
    const float a  = fabsf((float)op[b]);
    const float na = 1.0f - a;

    // ---- pos[b]: exactly one mask load per thread (S == NTH) ----
    int local = masks[(size_t)tid * B + b];

    // One-instruction warp reduction (REDUX.SUM).
    local = __reduce_add_sync(0xffffffffu, local);

    __shared__ int wsum[NTH / 32];       // 32 partials
    if ((tid & 31) == 0) wsum[tid >> 5] = local;
    __syncthreads();

    int pos = 0;
    #pragma unroll
    for (int w = 0; w < NTH / 32; w++) pos += wsum[w];

    const int prev = (pos == 0) ? S : pos - 1;   // mod(pos-1, S+1)

    // ---- Row select / blend: 512 threads per output, one float2 each ----
    const int half = tid >> 9;          // 0 = hidden, 1 = cell
    const int lane = tid & 511;         // float2 index in [0, 512) == H/2

    const size_t rowstride = (size_t)B * H;
    const float* data  = half ? cells     : hiddens;
    const float* initv = half ? init_cell : init_hidden;

    const float2* c2 = (const float2*)((pos  == 0) ? initv
                        : data + (size_t)(pos  - 1) * rowstride + (size_t)b * H);
    const float2* p2 = (const float2*)((prev == 0) ? initv
                        : data + (size_t)(prev - 1) * rowstride + (size_t)b * H);
    float2* d2 = (float2*)(out + (size_t)half * rowstride + (size_t)b * H);

    if (a == 1.0f) {
        d2[lane] = p2[lane];
    } else if (a == 0.0f) {
        d2[lane] = c2[lane];
    } else {
        float2 vp = p2[lane], vc = c2[lane], r;
        r.x = vp.x * a + vc.x * na;
        r.y = vp.y * a + vc.y * na;
        d2[lane] = r;
    }
}

// ---------------- Generic fallback (any S,B,H) ----------------
#define GTH 512

__global__ __launch_bounds__(GTH)
void lstm_state_kernel_generic(
    const float* __restrict__ hiddens,
    const float* __restrict__ cells,
    const float* __restrict__ init_hidden,
    const float* __restrict__ init_cell,
    const int*   __restrict__ masks,
    const int*   __restrict__ op,
    float* __restrict__ out,
    int S, int B, int H)
{
    const int b   = blockIdx.x;
    const int tid = threadIdx.x;

    const float a  = fabsf((float)op[b]);
    const float na = 1.0f - a;

    int local = 0;
    for (int s = tid; s < S; s += GTH)
        local += masks[(size_t)s * B + b];

    local = __reduce_add_sync(0xffffffffu, local);

    __shared__ int wsum[GTH / 32];
    if ((tid & 31) == 0) wsum[tid >> 5] = local;
    __syncthreads();

    int pos = 0;
    #pragma unroll
    for (int w = 0; w < GTH / 32; w++) pos += wsum[w];

    const int prev = (pos == 0) ? S : pos - 1;

    const size_t rowstride = (size_t)B * H;
    const int half = tid >> 8;
    const int lane = tid & 255;

    const float* data  = half ? cells     : hiddens;
    const float* initv = half ? init_cell : init_hidden;
    const float* cur_row  = (pos  == 0) ? initv
                          : data + (size_t)(pos  - 1) * rowstride + (size_t)b * H;
    const float* prev_row = (prev == 0) ? initv
                          : data + (size_t)(prev - 1) * rowstride + (size_t)b * H;
    float* dst = out + (size_t)half * rowstride + (size_t)b * H;

    for (int i = lane; i < H; i += 256)
        dst[i] = prev_row[i] * a + cur_row[i] * na;
}

extern "C" void kernel_launch(void* const* d_in, const int* in_sizes, int n_in,
                              void* d_out, int out_size)
{
    const float* hiddens     = (const float*)d_in[0];
    const float* cells       = (const float*)d_in[1];
    const float* init_hidden = (const float*)d_in[2];
    const float* init_cell   = (const float*)d_in[3];
    const int*   masks       = (const int*)d_in[4];
    const int*   op          = (const int*)d_in[5];
    float*       out         = (float*)d_out;

    const int H = in_sizes[2];          // init_hidden length
    const int B = in_sizes[5];          // op length
    const int S = in_sizes[4] / B;      // masks is [S,B]

    if (S == 1024 && H == 1024) {
        lstm_state_kernel_fast<<<B, NTH>>>(hiddens, cells, init_hidden, init_cell,
                                           masks, op, out, S, B, H);
    } else {
        lstm_state_kernel_generic<<<B, GTH>>>(hiddens, cells, init_hidden, init_cell,
                                              masks, op, out, S, B, H);
    }
}

// round 14
// speedup vs baseline: 1.0047x; 1.0047x over previous
#include <cuda_runtime.h>
#include <cuda_bf16.h>

// LSTMStateBufferCell — FINAL (round 14 == round 13 kernel, selection locked).
//
//   pos[b]  = sum_s hidden_masks[s,b]            (pos in [0,S])
//   prev    = mod(pos-1, S+1)
//   stack_X = [init_X ; X]  (index 0 = init row)
//   out_h[b,:] = stack_h[prev]*a + stack_h[pos]*(1-a),  a = |op[b]|
//   out_c[b,:] = stack_c[prev]*a + stack_c[pos]*(1-a)
// Output: f32 [2, B, H] (hidden then cell).
//
// Evidence summary (13 rounds): the bench is launch-overhead-bound; all sane
// kernels measure 6.59-6.92us. This configuration minimizes every remaining
// quantity with measured backing:
//   - pos: ONE mask LDG per thread (each of the 1024 mask lines touched
//     exactly once per block; R11 proved redundant strided reads cost ~6us)
//     -> one REDUX.SUM -> ONE __syncthreads (necessary; removal regresses)
//     -> serial sum of 32 warp partials (smem broadcasts).
//   - copy: 512 threads per output, exactly one float2 load + one float2
//     store each. a in {0,1} => pure row select (halves gather traffic);
//     general blend fallback preserved for any a.
//   - best profiled kernel time of all rounds: 6.34us, occ 52.9%.
// The reduce->gather dependency (two serial memory round-trips) is inherent:
// the gather address is a function of the full mask reduction.

#define NTH 1024

__global__ __launch_bounds__(NTH)
void lstm_state_kernel_fast(
    const float* __restrict__ hiddens,
    const float* __restrict__ cells,
    const float* __restrict__ init_hidden,
    const float* __restrict__ init_cell,
    const int*   __restrict__ masks,
    const int*   __restrict__ op,
    float* __restrict__ out,
    int S, int B, int H)     // S==1024, H==1024
{
    const int b   = blockIdx.x;
    const int tid = threadIdx.x;

    // Independent of the mask chain — issue first.
    const float a  = fabsf((float)op[b]);
    const float na = 1.0f - a;

    // ---- pos[b]: exactly one mask load per thread (S == NTH) ----
    int local = masks[(size_t)tid * B + b];

    // One-instruction warp reduction (REDUX.SUM).
    local = __reduce_add_sync(0xffffffffu, local);

    __shared__ int wsum[NTH / 32];       // 32 partials
    if ((tid & 31) == 0) wsum[tid >> 5] = local;
    __syncthreads();

    int pos = 0;
    #pragma unroll
    for (int w = 0; w < NTH / 32; w++) pos += wsum[w];

    const int prev = (pos == 0) ? S : pos - 1;   // mod(pos-1, S+1)

    // ---- Row select / blend: 512 threads per output, one float2 each ----
    const int half = tid >> 9;          // 0 = hidden, 1 = cell
    const int lane = tid & 511;         // float2 index in [0, 512) == H/2

    const size_t rowstride = (size_t)B * H;
    const float* data  = half ? cells     : hiddens;
    const float* initv = half ? init_cell : init_hidden;

    const float2* c2 = (const float2*)((pos  == 0) ? initv
                        : data + (size_t)(pos  - 1) * rowstride + (size_t)b * H);
    const float2* p2 = (const float2*)((prev == 0) ? initv
                        : data + (size_t)(prev - 1) * rowstride + (size_t)b * H);
    float2* d2 = (float2*)(out + (size_t)half * rowstride + (size_t)b * H);

    if (a == 1.0f) {
        d2[lane] = p2[lane];
    } else if (a == 0.0f) {
        d2[lane] = c2[lane];
    } else {
        float2 vp = p2[lane], vc = c2[lane], r;
        r.x = vp.x * a + vc.x * na;
        r.y = vp.y * a + vc.y * na;
        d2[lane] = r;
    }
}

// ---------------- Generic fallback (any S,B,H) ----------------
#define GTH 512

__global__ __launch_bounds__(GTH)
void lstm_state_kernel_generic(
    const float* __restrict__ hiddens,
    const float* __restrict__ cells,
    const float* __restrict__ init_hidden,
    const float* __restrict__ init_cell,
    const int*   __restrict__ masks,
    const int*   __restrict__ op,
    float* __restrict__ out,
    int S, int B, int H)
{
    const int b   = blockIdx.x;
    const int tid = threadIdx.x;

    const float a  = fabsf((float)op[b]);
    const float na = 1.0f - a;

    int local = 0;
    for (int s = tid; s < S; s += GTH)
        local += masks[(size_t)s * B + b];

    local = __reduce_add_sync(0xffffffffu, local);

    __shared__ int wsum[GTH / 32];
    if ((tid & 31) == 0) wsum[tid >> 5] = local;
    __syncthreads();

    int pos = 0;
    #pragma unroll
    for (int w = 0; w < GTH / 32; w++) pos += wsum[w];

    const int prev = (pos == 0) ? S : pos - 1;

    const size_t rowstride = (size_t)B * H;
    const int half = tid >> 8;
    const int lane = tid & 255;

    const float* data  = half ? cells     : hiddens;
    const float* initv = half ? init_cell : init_hidden;
    const float* cur_row  = (pos  == 0) ? initv
                          : data + (size_t)(pos  - 1) * rowstride + (size_t)b * H;
    const float* prev_row = (prev == 0) ? initv
                          : data + (size_t)(prev - 1) * rowstride + (size_t)b * H;
    float* dst = out + (size_t)half * rowstride + (size_t)b * H;

    for (int i = lane; i < H; i += 256)
        dst[i] = prev_row[i] * a + cur_row[i] * na;
}

extern "C" void kernel_launch(void* const* d_in, const int* in_sizes, int n_in,
                              void* d_out, int out_size)
{
    const float* hiddens     = (const float*)d_in[0];
    const float* cells       = (const float*)d_in[1];
    const float* init_hidden = (const float*)d_in[2];
    const float* init_cell   = (const float*)d_in[3];
    const int*   masks       = (const int*)d_in[4];
    const int*   op          = (const int*)d_in[5];
    float*       out         = (float*)d_out;

    const int H = in_sizes[2];          // init_hidden length
    const int B = in_sizes[5];          // op length
    const int S = in_sizes[4] / B;      // masks is [S,B]

    if (S == 1024 && H == 1024) {
        lstm_state_kernel_fast<<<B, NTH>>>(hiddens, cells, init_hidden, init_cell,
                                           masks, op, out, S, B, H);
    } else {
        lstm_state_kernel_generic<<<B, GTH>>>(hiddens, cells, init_hidden, init_cell,
                                              masks, op, out, S, B, H);
    }
}